// round 1
// baseline (speedup 1.0000x reference)
#include <cuda_runtime.h>

// Problem constants (from reference setup_inputs)
constexpr int B = 2;
constexpr int D = 160;
constexpr int H = 192;
constexpr int W = 160;
constexpr int HW = H * W;            // 30720
constexpr int N = D * H * W;         // 4,915,200 voxels per batch

__device__ __forceinline__ float sample_trilinear(const float* __restrict__ s,
                                                  float z, float y, float x) {
    float z0f = floorf(z), y0f = floorf(y), x0f = floorf(x);
    int z0 = (int)z0f, y0 = (int)y0f, x0 = (int)x0f;
    float wz1 = z - z0f, wy1 = y - y0f, wx1 = x - x0f;
    float wz0 = 1.0f - wz1, wy0 = 1.0f - wy1, wx0 = 1.0f - wx1;

    float acc = 0.0f;
#pragma unroll
    for (int iz = 0; iz < 2; ++iz) {
        int zi = z0 + iz;
        float wz = iz ? wz1 : wz0;
        bool zin = (zi >= 0) & (zi < D);
        int zoff = zi * HW;
#pragma unroll
        for (int iy = 0; iy < 2; ++iy) {
            int yi = y0 + iy;
            float wy = iy ? wy1 : wy0;
            bool yin = (yi >= 0) & (yi < H);
            int yoff = zoff + yi * W;
#pragma unroll
            for (int ix = 0; ix < 2; ++ix) {
                int xi = x0 + ix;
                float wx = ix ? wx1 : wx0;
                bool xin = (xi >= 0) & (xi < W);
                float v = 0.0f;
                if (zin & yin & xin) v = __ldg(s + yoff + xi);
                acc = fmaf(v, wz * wy * wx, acc);
            }
        }
    }
    return acc;
}

__global__ void warp3d_kernel(const float* __restrict__ src,
                              const float* __restrict__ flow,
                              float* __restrict__ out) {
    int tid = blockIdx.x * blockDim.x + threadIdx.x;
    constexpr int total4 = (B * N) / 4;
    if (tid >= total4) return;

    int i4 = tid * 4;
    int b = i4 / N;
    int r = i4 - b * N;            // voxel index within batch, multiple of 4
    int d = r / HW;
    int hw = r - d * HW;
    int h = hw / W;
    int w = hw - h * W;

    const float* fbase = flow + (size_t)b * 3 * N + r;
    float4 fz = *reinterpret_cast<const float4*>(fbase);
    float4 fy = *reinterpret_cast<const float4*>(fbase + N);
    float4 fx = *reinterpret_cast<const float4*>(fbase + 2 * N);

    // coord = (id + flow) * S/(S-1) - 0.5
    constexpr float sz = (float)D / (float)(D - 1);
    constexpr float sy = (float)H / (float)(H - 1);
    constexpr float sx = (float)W / (float)(W - 1);

    const float* s = src + (size_t)b * N;

    float fzv[4] = {fz.x, fz.y, fz.z, fz.w};
    float fyv[4] = {fy.x, fy.y, fy.z, fy.w};
    float fxv[4] = {fx.x, fx.y, fx.z, fx.w};

    float4 o;
    float ov[4];
#pragma unroll
    for (int k = 0; k < 4; ++k) {
        float z = fmaf((float)d + fzv[k], sz, -0.5f);
        float y = fmaf((float)h + fyv[k], sy, -0.5f);
        float x = fmaf((float)(w + k) + fxv[k], sx, -0.5f);
        ov[k] = sample_trilinear(s, z, y, x);
    }
    o.x = ov[0]; o.y = ov[1]; o.z = ov[2]; o.w = ov[3];
    *reinterpret_cast<float4*>(out + (size_t)b * N + r) = o;
}

extern "C" void kernel_launch(void* const* d_in, const int* in_sizes, int n_in,
                              void* d_out, int out_size) {
    const float* src = (const float*)d_in[0];
    const float* flow = (const float*)d_in[1];
    float* out = (float*)d_out;

    constexpr int total4 = (B * N) / 4;     // 2,457,600 threads
    constexpr int threads = 256;
    constexpr int blocks = (total4 + threads - 1) / threads;
    warp3d_kernel<<<blocks, threads>>>(src, flow, out);
}